// round 1
// baseline (speedup 1.0000x reference)
#include <cuda_runtime.h>
#include <math.h>

// Problem constants
#define TT 2048
#define BB 8
#define DD 1024
#define NS 1024          // N_STATE
#define NBLK 128         // NB
#define MM (TT*BB)       // 16384 rows for projections

// Scratch: k, v, q projections [T*B, NS] fp32 (device globals: no cudaMalloc allowed)
__device__ float g_k[(size_t)MM * NS];
__device__ float g_v[(size_t)MM * NS];
__device__ float g_q[(size_t)MM * NS];

// ---------------------------------------------------------------------------
// Packed fp32x2 helpers (Blackwell: scalar FFMA is half-rate; f32x2 is full)
// ---------------------------------------------------------------------------
static __device__ __forceinline__ unsigned long long pk2(float lo, float hi) {
    unsigned long long r;
    asm("mov.b64 %0, {%1, %2};" : "=l"(r) : "f"(lo), "f"(hi));
    return r;
}
static __device__ __forceinline__ void fma2(unsigned long long& d,
                                            unsigned long long a,
                                            unsigned long long b) {
    asm("fma.rn.f32x2 %0, %1, %2, %0;" : "+l"(d) : "l"(a), "l"(b));
}
static __device__ __forceinline__ void upk2(unsigned long long v, float& lo, float& hi) {
    asm("mov.b64 {%0, %1}, %2;" : "=f"(lo), "=f"(hi) : "l"(v));
}

// ---------------------------------------------------------------------------
// GEMM: C[m, n] = sum_d X[m, d] * W[n, d]   (both K-major, "NT" layout)
// Tile 128x128, BK=16, 256 threads, 8x8 micro-tile per thread with f32x2 acc.
// blockIdx.z selects (W_k, W_v, W_q) -> (g_k, g_v, g_q).
// ---------------------------------------------------------------------------
#define GBK 16

__global__ void __launch_bounds__(256)
gemm3_kernel(const float* __restrict__ X,
             const float* __restrict__ Wk,
             const float* __restrict__ Wv,
             const float* __restrict__ Wq)
{
    __shared__ float As[GBK][128];
    __shared__ float Bs[GBK][128];

    const float* W = (blockIdx.z == 0) ? Wk : ((blockIdx.z == 1) ? Wv : Wq);
    float*       C = (blockIdx.z == 0) ? g_k : ((blockIdx.z == 1) ? g_v : g_q);

    const int bm = blockIdx.y * 128;
    const int bn = blockIdx.x * 128;
    const int tid = threadIdx.x;
    const int tx = tid & 15;   // 0..15 -> 8 output cols each
    const int ty = tid >> 4;   // 0..15 -> 8 output rows each

    unsigned long long acc[8][4];
#pragma unroll
    for (int i = 0; i < 8; i++)
#pragma unroll
        for (int j = 0; j < 4; j++) acc[i][j] = 0ull;

    for (int k0 = 0; k0 < DD; k0 += GBK) {
        // Cooperative load: 128x16 A and B tiles, transposed into smem [k][row]
#pragma unroll
        for (int l = 0; l < 2; l++) {
            int v  = tid + l * 256;          // 0..511 -> 512 float4 slots
            int r  = v >> 2;                 // 0..127
            int cc = (v & 3) * 4;            // 0,4,8,12
            float4 a = *(const float4*)(X + (size_t)(bm + r) * DD + k0 + cc);
            As[cc + 0][r] = a.x; As[cc + 1][r] = a.y;
            As[cc + 2][r] = a.z; As[cc + 3][r] = a.w;
            float4 b = *(const float4*)(W + (size_t)(bn + r) * DD + k0 + cc);
            Bs[cc + 0][r] = b.x; Bs[cc + 1][r] = b.y;
            Bs[cc + 2][r] = b.z; Bs[cc + 3][r] = b.w;
        }
        __syncthreads();

#pragma unroll
        for (int kk = 0; kk < GBK; kk++) {
            float4 a0 = *(const float4*)&As[kk][ty * 8];
            float4 a1 = *(const float4*)&As[kk][ty * 8 + 4];
            float4 b0 = *(const float4*)&Bs[kk][tx * 8];
            float4 b1 = *(const float4*)&Bs[kk][tx * 8 + 4];
            unsigned long long bp[4] = { pk2(b0.x, b0.y), pk2(b0.z, b0.w),
                                         pk2(b1.x, b1.y), pk2(b1.z, b1.w) };
            float av[8] = { a0.x, a0.y, a0.z, a0.w, a1.x, a1.y, a1.z, a1.w };
#pragma unroll
            for (int i = 0; i < 8; i++) {
                unsigned long long ad = pk2(av[i], av[i]);
#pragma unroll
                for (int jp = 0; jp < 4; jp++) fma2(acc[i][jp], ad, bp[jp]);
            }
        }
        __syncthreads();
    }

    // Epilogue: unpack and store 8x8 tile as float4 pairs
#pragma unroll
    for (int i = 0; i < 8; i++) {
        float o[8];
        upk2(acc[i][0], o[0], o[1]);
        upk2(acc[i][1], o[2], o[3]);
        upk2(acc[i][2], o[4], o[5]);
        upk2(acc[i][3], o[6], o[7]);
        float* cp = C + (size_t)(bm + ty * 8 + i) * NS + bn + tx * 8;
        *(float4*)(cp)     = make_float4(o[0], o[1], o[2], o[3]);
        *(float4*)(cp + 4) = make_float4(o[4], o[5], o[6], o[7]);
    }
}

// ---------------------------------------------------------------------------
// Recurrent delta-rule scan. 1024 independent chains (b, nb), each an 8x8
// state. 8 lanes per chain: lane i holds state row S[i][0..7] in registers.
// 64 threads/block = 8 chains; 128 blocks total. Software prefetch of next
// step's k/q/v keeps global-load latency off the recurrence critical path.
// ---------------------------------------------------------------------------
__global__ void __launch_bounds__(64)
scan_kernel(float* __restrict__ out, int write_sf)
{
    const int c    = blockIdx.x * 8 + (threadIdx.x >> 3);  // chain id 0..1023
    const int lane = threadIdx.x & 7;                      // state row
    const int b  = c >> 7;      // / NBLK
    const int nb = c & 127;

    const float* kp = g_k + (size_t)b * NS + nb * 8;
    const float* qp = g_q + (size_t)b * NS + nb * 8;
    const float* vp = g_v + (size_t)b * NS + nb * 8 + lane;
    float*       op = out + (size_t)b * NS + nb * 8 + lane;

    const int stride = BB * NS;  // 8192 floats per time step

    float S[8];
#pragma unroll
    for (int j = 0; j < 8; j++) S[j] = 0.0f;

    // prefetch t = 0
    float4 ka = *(const float4*)(kp);
    float4 kb = *(const float4*)(kp + 4);
    float4 qa = *(const float4*)(qp);
    float4 qb = *(const float4*)(qp + 4);
    float  vv = *vp;

    for (int t = 0; t < TT; t++) {
        float kc[8] = { ka.x, ka.y, ka.z, ka.w, kb.x, kb.y, kb.z, kb.w };
        float qc[8] = { qa.x, qa.y, qa.z, qa.w, qb.x, qb.y, qb.z, qb.w };
        float vc = vv;

        if (t + 1 < TT) {  // prefetch next step (independent of S-chain)
            const float* kn_ = kp + (size_t)(t + 1) * stride;
            const float* qn_ = qp + (size_t)(t + 1) * stride;
            ka = *(const float4*)(kn_);
            kb = *(const float4*)(kn_ + 4);
            qa = *(const float4*)(qn_);
            qb = *(const float4*)(qn_ + 4);
            vv = vp[(size_t)(t + 1) * stride];
        }

        // k_norm = k / (||k|| + 1e-6)
        float ss = 0.0f;
#pragma unroll
        for (int j = 0; j < 8; j++) ss = fmaf(kc[j], kc[j], ss);
        float inv = 1.0f / (sqrtf(ss) + 1e-6f);
#pragma unroll
        for (int j = 0; j < 8; j++) kc[j] *= inv;

        // retrieved_i = dot(S_i, k_norm); delta_i = v_i - retrieved
        float r = 0.0f;
#pragma unroll
        for (int j = 0; j < 8; j++) r = fmaf(S[j], kc[j], r);
        float delta = vc - r;

        // S = tanh(S + delta * k_norm)
#pragma unroll
        for (int j = 0; j < 8; j++) S[j] = tanhf(fmaf(delta, kc[j], S[j]));

        // Sq_i = dot(S_i, q); out = Sq^2 * sigmoid(Sq)
        float sq = 0.0f;
#pragma unroll
        for (int j = 0; j < 8; j++) sq = fmaf(S[j], qc[j], sq);
        float y = sq * sq * (1.0f / (1.0f + expf(-sq)));

        op[(size_t)t * stride] = y;
    }

    if (write_sf) {
        // S_final layout [B, NB, 8, 8] appended after outputs
        float* sf = out + (size_t)MM * NS + (size_t)c * 64 + lane * 8;
#pragma unroll
        for (int j = 0; j < 8; j++) sf[j] = S[j];
    }
}

// ---------------------------------------------------------------------------
extern "C" void kernel_launch(void* const* d_in, const int* in_sizes, int n_in,
                              void* d_out, int out_size)
{
    (void)in_sizes; (void)n_in;
    const float* x  = (const float*)d_in[0];
    const float* wk = (const float*)d_in[1];
    const float* wv = (const float*)d_in[2];
    const float* wq = (const float*)d_in[3];
    float* out = (float*)d_out;

    dim3 grid(NS / 128, MM / 128, 3);
    gemm3_kernel<<<grid, 256>>>(x, wk, wv, wq);

    const long long n_out   = (long long)MM * NS;           // 16,777,216
    const long long n_state = (long long)BB * NBLK * 64;    // 65,536
    int write_sf = ((long long)out_size >= n_out + n_state) ? 1 : 0;

    scan_kernel<<<128, 64>>>(out, write_sf);
}

// round 3
// speedup vs baseline: 1.7526x; 1.7526x over previous
#include <cuda_runtime.h>
#include <cuda_bf16.h>
#include <math.h>
#include <stdint.h>

// Problem constants
#define TT 2048
#define BB 8
#define DD 1024
#define NS 1024
#define NBLK 128
#define MM (TT*BB)        // 16384 projection rows
#define KP 3072           // K' = 3*D  (bf16x3 split concatenated along K)
#define NP 3072           // N' = 3*N_STATE (k,v,q concatenated along N)

// Scratch (device globals: no cudaMalloc allowed)
__device__ __nv_bfloat16 g_A[(size_t)MM * KP];   // [Ah | Ah | Al]
__device__ __nv_bfloat16 g_B[(size_t)NP * KP];   // rows: Wk,Wv,Wq; cols: [Bh | Bl | Bh]
__device__ float         g_P[(size_t)MM * NP];   // cols 0-1023=k, 1024-2047=v, 2048-3071=q

// ---------------------------------------------------------------------------
// Helpers
// ---------------------------------------------------------------------------
static __device__ __forceinline__ uint32_t smem_u32(const void* p) {
    uint32_t a;
    asm("{ .reg .u64 t; cvta.to.shared.u64 t, %1; cvt.u32.u64 %0, t; }" : "=r"(a) : "l"(p));
    return a;
}
#define SWZ(off) ((off) ^ (((off) >> 3) & 0x70))

#define CP_ASYNC16(saddr, gaddr) \
    asm volatile("cp.async.cg.shared.global [%0], [%1], 16;" :: "r"(saddr), "l"(gaddr))
#define CP_COMMIT() asm volatile("cp.async.commit_group;" ::: "memory")
#define CP_WAIT(n)  asm volatile("cp.async.wait_group %0;" :: "n"(n) : "memory")

#define LDSM_X4(r0, r1, r2, r3, addr) \
    asm volatile("ldmatrix.sync.aligned.m8n8.x4.shared.b16 {%0,%1,%2,%3}, [%4];" \
                 : "=r"(r0), "=r"(r1), "=r"(r2), "=r"(r3) : "r"(addr))

static __device__ __forceinline__ void mma16816(float* d, const uint32_t* a,
                                                const uint32_t* b) {
    asm volatile(
        "mma.sync.aligned.m16n8k16.row.col.f32.bf16.bf16.f32 "
        "{%0,%1,%2,%3}, {%4,%5,%6,%7}, {%8,%9}, {%0,%1,%2,%3};"
        : "+f"(d[0]), "+f"(d[1]), "+f"(d[2]), "+f"(d[3])
        : "r"(a[0]), "r"(a[1]), "r"(a[2]), "r"(a[3]), "r"(b[0]), "r"(b[1]));
}

// ---------------------------------------------------------------------------
// Conversion: fp32 -> bf16 hi/lo split, concatenated along K
// ---------------------------------------------------------------------------
static __device__ __forceinline__ uint2 pack4(const float* f, bool lo_part) {
    unsigned short h[4];
#pragma unroll
    for (int j = 0; j < 4; j++) {
        __nv_bfloat16 hi = __float2bfloat16(f[j]);
        if (!lo_part) h[j] = __bfloat16_as_ushort(hi);
        else          h[j] = __bfloat16_as_ushort(__float2bfloat16(f[j] - __bfloat162float(hi)));
    }
    uint2 r;
    r.x = (uint32_t)h[0] | ((uint32_t)h[1] << 16);
    r.y = (uint32_t)h[2] | ((uint32_t)h[3] << 16);
    return r;
}

__global__ void __launch_bounds__(256)
convert_x_kernel(const float* __restrict__ X) {
    size_t i = (size_t)blockIdx.x * 256 + threadIdx.x;   // unit = 4 floats
    size_t e = i * 4;
    size_t m = e / DD;
    int    c = (int)(e % DD);
    float4 a = *(const float4*)(X + e);
    float f[4] = {a.x, a.y, a.z, a.w};
    uint2 hp = pack4(f, false);
    uint2 lp = pack4(f, true);
    __nv_bfloat16* row = g_A + m * KP;
    *(uint2*)(row + c)        = hp;   // segment 0: Ah
    *(uint2*)(row + c + DD)   = hp;   // segment 1: Ah
    *(uint2*)(row + c + 2*DD) = lp;   // segment 2: Al
}

__global__ void __launch_bounds__(256)
convert_w_kernel(const float* __restrict__ Wk, const float* __restrict__ Wv,
                 const float* __restrict__ Wq) {
    size_t i = (size_t)blockIdx.x * 256 + threadIdx.x;
    size_t e = i * 4;
    int    w = (int)(e / ((size_t)NS * DD));
    size_t r = e % ((size_t)NS * DD);
    const float* W = (w == 0) ? Wk : ((w == 1) ? Wv : Wq);
    size_t n = r / DD;
    int    c = (int)(r % DD);
    float4 a = *(const float4*)(W + r);
    float f[4] = {a.x, a.y, a.z, a.w};
    uint2 hp = pack4(f, false);
    uint2 lp = pack4(f, true);
    __nv_bfloat16* row = g_B + ((size_t)w * NS + n) * KP;
    *(uint2*)(row + c)        = hp;   // segment 0: Bh
    *(uint2*)(row + c + DD)   = lp;   // segment 1: Bl
    *(uint2*)(row + c + 2*DD) = hp;   // segment 2: Bh
}

// ---------------------------------------------------------------------------
// bf16 GEMM via mma.sync: g_P[m,n] = sum_k g_A[m,k] * g_B[n,k]
// CTA tile 128x128, BK=64 (SW128 rows), 3-stage cp.async pipeline,
// 8 warps x (64x32) warp tiles, m16n8k16 HMMA, fp32 accum.
// ---------------------------------------------------------------------------
#define TM 128
#define TN 128
#define CK 64
#define NCH (KP / CK)     // 48
#define STAGES 3
#define STG_BYTES (2 * TM * CK * 2)       // A tile + B tile = 32768
#define GEMM_SMEM (STAGES * STG_BYTES)    // 98304

__global__ void __launch_bounds__(256, 2)
gemm_kernel() {
    extern __shared__ char smem[];
    const uint32_t sb  = smem_u32(smem);
    const int tid = threadIdx.x;
    const int wid = tid >> 5;
    const int lid = tid & 31;
    const size_t bm = (size_t)blockIdx.y * TM;
    const size_t bn = (size_t)blockIdx.x * TN;

    const int wm = wid & 1;          // 2 M-slabs of 64
    const int wn = wid >> 1;         // 4 N-slabs of 32

    // cp.async source bases
    const __nv_bfloat16* Abase = g_A + bm * KP;
    const __nv_bfloat16* Bbase = g_B + bn * KP;

    // per-thread load mapping: 4 units A + 4 units B per stage
    // unit = tid + u*256: r = unit>>3 (0..127), c = unit&7 (16B chunk)
    auto issue_stage = [&](int i) {
        const uint32_t abuf = sb + (i % STAGES) * STG_BYTES;
        const uint32_t bbuf = abuf + TM * CK * 2;
        const __nv_bfloat16* As = Abase + i * CK;
        const __nv_bfloat16* Bs = Bbase + i * CK;
#pragma unroll
        for (int u = 0; u < 4; u++) {
            int unit = tid + u * 256;
            int r = unit >> 3, c = unit & 7;
            uint32_t off = SWZ(r * 128 + c * 16);
            CP_ASYNC16(abuf + off, (const char*)(As + (size_t)r * KP + c * 8));
            CP_ASYNC16(bbuf + off, (const char*)(Bs + (size_t)r * KP + c * 8));
        }
        CP_COMMIT();
    };

    // prologue: stages 0,1 in flight
    issue_stage(0);
    issue_stage(1);

    float acc[4][4][4];
#pragma unroll
    for (int i = 0; i < 4; i++)
#pragma unroll
        for (int j = 0; j < 4; j++)
#pragma unroll
            for (int r = 0; r < 4; r++) acc[i][j][r] = 0.0f;

    // ldmatrix per-lane row/chunk pattern
    const int lrow   = (lid & 7) + ((lid >> 3) & 1) * 8;  // row within 16-row group
    const int chalf  = lid >> 4;                          // 16B chunk half (0/1)

    for (int it = 0; it < NCH; it++) {
        CP_WAIT(1);                 // stage `it` resident
        __syncthreads();            // all warps done with buffer (it-1)%3
        if (it + 2 < NCH) issue_stage(it + 2);

        const uint32_t abuf = sb + (it % STAGES) * STG_BYTES;
        const uint32_t bbuf = abuf + TM * CK * 2;

#pragma unroll
        for (int s = 0; s < 4; s++) {          // k16 steps within CK=64
            const int ch = 2 * s + chalf;      // 16B chunk index (0..7)
            uint32_t a[4][4];
#pragma unroll
            for (int mf = 0; mf < 4; mf++) {
                uint32_t addr = abuf + SWZ((wm * 64 + mf * 16 + lrow) * 128 + ch * 16);
                LDSM_X4(a[mf][0], a[mf][1], a[mf][2], a[mf][3], addr);
            }
            uint32_t b[2][4];
#pragma unroll
            for (int nf2 = 0; nf2 < 2; nf2++) {
                uint32_t addr = bbuf + SWZ((wn * 32 + nf2 * 16 + lrow) * 128 + ch * 16);
                LDSM_X4(b[nf2][0], b[nf2][1], b[nf2][2], b[nf2][3], addr);
            }
#pragma unroll
            for (int mf = 0; mf < 4; mf++) {
#pragma unroll
                for (int nf = 0; nf < 4; nf++) {
                    uint32_t bb_[2] = { b[nf >> 1][(nf & 1)], b[nf >> 1][(nf & 1) + 2] };
                    mma16816(acc[mf][nf], a[mf], bb_);
                }
            }
        }
        __syncthreads();
    }

    // Epilogue: direct float2 stores
    const int r0 = lid >> 2;        // 0..7
    const int cp = (lid & 3) * 2;   // col pair
#pragma unroll
    for (int mf = 0; mf < 4; mf++) {
#pragma unroll
        for (int nf = 0; nf < 4; nf++) {
            float* dst = g_P + (bm + wm * 64 + mf * 16 + r0) * (size_t)NP
                             + bn + wn * 32 + nf * 8 + cp;
            *(float2*)dst = make_float2(acc[mf][nf][0], acc[mf][nf][1]);
            *(float2*)(dst + 8 * NP) = make_float2(acc[mf][nf][2], acc[mf][nf][3]);
        }
    }
}

// ---------------------------------------------------------------------------
// Recurrent delta-rule scan
// ---------------------------------------------------------------------------
__global__ void __launch_bounds__(64)
scan_kernel(float* __restrict__ out, int write_sf)
{
    const int c    = blockIdx.x * 8 + (threadIdx.x >> 3);  // chain 0..1023
    const int lane = threadIdx.x & 7;
    const int b  = c >> 7;
    const int nb = c & 127;

    const float* kp = g_P + (size_t)b * NP + nb * 8;
    const float* vp = g_P + (size_t)b * NP + NS + nb * 8 + lane;
    const float* qp = g_P + (size_t)b * NP + 2 * NS + nb * 8;
    float*       op = out + (size_t)b * NS + nb * 8 + lane;

    const int pstride = BB * NP;
    const int ostride = BB * NS;

    float S[8];
#pragma unroll
    for (int j = 0; j < 8; j++) S[j] = 0.0f;

    float4 ka = *(const float4*)(kp);
    float4 kb = *(const float4*)(kp + 4);
    float4 qa = *(const float4*)(qp);
    float4 qb = *(const float4*)(qp + 4);
    float  vv = *vp;

    for (int t = 0; t < TT; t++) {
        float kc[8] = { ka.x, ka.y, ka.z, ka.w, kb.x, kb.y, kb.z, kb.w };
        float qc[8] = { qa.x, qa.y, qa.z, qa.w, qb.x, qb.y, qb.z, qb.w };
        float vc = vv;

        if (t + 1 < TT) {
            const float* kn_ = kp + (size_t)(t + 1) * pstride;
            const float* qn_ = qp + (size_t)(t + 1) * pstride;
            ka = *(const float4*)(kn_);
            kb = *(const float4*)(kn_ + 4);
            qa = *(const float4*)(qn_);
            qb = *(const float4*)(qn_ + 4);
            vv = vp[(size_t)(t + 1) * pstride];
        }

        float ss = 0.0f;
#pragma unroll
        for (int j = 0; j < 8; j++) ss = fmaf(kc[j], kc[j], ss);
        float inv = 1.0f / (sqrtf(ss) + 1e-6f);
#pragma unroll
        for (int j = 0; j < 8; j++) kc[j] *= inv;

        float r = 0.0f;
#pragma unroll
        for (int j = 0; j < 8; j++) r = fmaf(S[j], kc[j], r);
        float delta = vc - r;

#pragma unroll
        for (int j = 0; j < 8; j++) S[j] = tanhf(fmaf(delta, kc[j], S[j]));

        float sq = 0.0f;
#pragma unroll
        for (int j = 0; j < 8; j++) sq = fmaf(S[j], qc[j], sq);
        float y = sq * sq * (1.0f / (1.0f + expf(-sq)));

        op[(size_t)t * ostride] = y;
    }

    if (write_sf) {
        float* sf = out + (size_t)MM * NS + (size_t)c * 64 + lane * 8;
#pragma unroll
        for (int j = 0; j < 8; j++) sf[j] = S[j];
    }
}

// ---------------------------------------------------------------------------
extern "C" void kernel_launch(void* const* d_in, const int* in_sizes, int n_in,
                              void* d_out, int out_size)
{
    (void)in_sizes; (void)n_in;
    const float* x  = (const float*)d_in[0];
    const float* wk = (const float*)d_in[1];
    const float* wv = (const float*)d_in[2];
    const float* wq = (const float*)d_in[3];
    float* out = (float*)d_out;

    convert_x_kernel<<<(MM * DD / 4) / 256, 256>>>(x);
    convert_w_kernel<<<(3 * NS * DD / 4) / 256, 256>>>(wk, wv, wq);

    cudaFuncSetAttribute(gemm_kernel, cudaFuncAttributeMaxDynamicSharedMemorySize, GEMM_SMEM);
    dim3 ggrid(NP / TN, MM / TM);   // 24 x 128
    gemm_kernel<<<ggrid, 256, GEMM_SMEM>>>();

    const long long n_out   = (long long)MM * NS;
    const long long n_state = (long long)BB * NBLK * 64;
    int write_sf = ((long long)out_size >= n_out + n_state) ? 1 : 0;
    scan_kernel<<<128, 64>>>(out, write_sf);
}